// round 16
// baseline (speedup 1.0000x reference)
#include <cuda_runtime.h>
#include <cuda_fp16.h>
#include <math.h>
#include <stdint.h>

#define BB   8
#define LL   512
#define BL   4096      // B*L
#define DM   768
#define DI   1536
#define NS   16
#define DTR  48
#define KSP  7
#define DCV  4

// ---------------- scratch (device globals; no allocation allowed) ----------
__device__ float g_xz[BL * 2 * DI];
__device__ float g_xmc[BL * DI];
__device__ float g_xdbl[BL * 80];
__device__ float g_dtb[BL * DI];
__device__ float g_cat[BL * 2 * DM];   // [xgcn | xmamba]
__device__ float g_tmp[BL * DM];
__device__ float g_cbias[DM];          // conv_b + gcn_b
__device__ float g_gateb[DM];          // gg_b + gm_b

// fp16 activation buffers (GEMM A inputs)
__device__ __half g_xnh[BL * DM];
__device__ __half g_xmch[BL * DI];
__device__ __half g_xdblh[BL * 80];
__device__ __half g_yh[BL * DI];
__device__ __half g_cath[BL * 2 * DM];
__device__ __half g_fusedh[BL * DM];

// pre-transposed weights: [N][K] fp16
__device__ __half g_wT_in[2 * DI * DM];
__device__ __half g_wT_dt[DI * DTR];
__device__ __half g_wT_out[DM * DI];
__device__ __half g_wT_ggm[DM * 2 * DM];
__device__ __half g_wT_o[DM * DM];
__device__ __half g_wT_xp[80 * DI];
__device__ __half g_wT_cv[DM * 8 * DM];   // 7 conv taps + gcn

// ===================== helpers =============================================
__device__ __forceinline__ uint32_t s2u(const void* p) {
    uint32_t a;
    asm("{ .reg .u64 t; cvta.to.shared.u64 t, %1; cvt.u32.u64 %0, t; }" : "=r"(a) : "l"(p));
    return a;
}
__device__ __forceinline__ void ldsm4(uint32_t& r0, uint32_t& r1, uint32_t& r2, uint32_t& r3,
                                      uint32_t addr) {
    asm volatile("ldmatrix.sync.aligned.m8n8.x4.shared.b16 {%0,%1,%2,%3}, [%4];"
        : "=r"(r0), "=r"(r1), "=r"(r2), "=r"(r3) : "r"(addr));
}
__device__ __forceinline__ void mma_f16(float& c0, float& c1, float& c2, float& c3,
                                        const uint32_t* a, const uint32_t* b) {
    asm volatile("mma.sync.aligned.m16n8k16.row.col.f32.f16.f16.f32 "
        "{%0,%1,%2,%3}, {%4,%5,%6,%7}, {%8,%9}, {%0,%1,%2,%3};"
        : "+f"(c0), "+f"(c1), "+f"(c2), "+f"(c3)
        : "r"(a[0]), "r"(a[1]), "r"(a[2]), "r"(a[3]), "r"(b[0]), "r"(b[1]));
}
__device__ __forceinline__ void cp16(uint32_t dst, const void* src, int sz) {
    asm volatile("cp.async.cg.shared.global [%0], [%1], 16, %2;"
        :: "r"(dst), "l"(src), "r"(sz));
}
#define CP_COMMIT() asm volatile("cp.async.commit_group;" ::: "memory")
#define CP_WAIT0()  asm volatile("cp.async.wait_group 0;" ::: "memory")

// smem tiles: A 64 rows x 64 f16, B 128 rows x 64 f16, row stride 144B
constexpr int ROWB = 144;
constexpr int ATILE = 64 * ROWB;                   // 9216
constexpr int BTILE = 128 * ROWB;                  // 18432
constexpr int OFF_A = 0, OFF_B = ATILE;
constexpr int SSTR = ATILE + BTILE;                // 27648
constexpr int MG_SMEM = 2 * SSTR;                  // 55296 -> 4 CTAs/SM

// ===================== tensor-core GEMM body (mma.sync fp16) ===============
// C[M,N] = A[M,K] @ BT[N,K]^T ; A fp16, BT fp16, fp32 accumulate.
// Block tile 64(M) x 128(N), K-tile 64, double-buffered cp.async.
// MODEA: 0 = A from Ah; 1 = conv-shifted gather of g_xnh (K=8*DM).
// ACT: 0=none, 1=softplus, 2=gated fusion. WF/WH: fp32 / fp16 C writes.
template<int MODEA, bool BIAS, int ACT, bool NGUARD, bool WF, bool WH>
__device__ __forceinline__ void mgemm_body(
    const __half* __restrict__ Ah, int lda,
    const __half* __restrict__ Bh,
    const float* __restrict__ bias,
    float* __restrict__ Cf, __half* __restrict__ Ch,
    int ldc, int N, int K,
    const float* __restrict__ Afp, int ldafp,
    int bm, int bn, char* smem)
{
    const uint32_t smemU = s2u(smem);
    const int tid = threadIdx.x, wid = tid >> 5, lane = tid & 31;

    // A loader: thread t -> row t>>2, chunks (t&3) and (t&3)+4 (16B each)
    const int arow = tid >> 2;
    const int acq  = (tid & 3);
    const int ar = bm + arow;
    const int cb = ar >> 9, clv = ar & 511;   // conv coords
    const uint32_t sbaseA = arow * ROWB + acq * 16;
    // B loader: thread t -> row t>>1, 64B half (t&1) = 4 chunks
    const int brow = tid >> 1;
    const int bcq  = (tid & 1);
    const int brn = bn + brow;
    const uint32_t sbaseB = brow * ROWB + bcq * 64;

    const int nk = (K + 63) >> 6;

    auto cpAll = [&](int kt, int stg) {
        const uint32_t base = smemU + stg * SSTR;
        const int kbase = kt * 64;
        // ---- A (2 cp16) ----
        if (MODEA == 0) {
            #pragma unroll
            for (int c = 0; c < 2; c++) {
                int k0 = kbase + acq * 8 + c * 32;
                bool ok = (k0 < K);
                const __half* pa = ok ? Ah + (size_t)ar * lda + k0 : g_xnh;
                cp16(base + OFF_A + sbaseA + c * 64, pa, ok ? 16 : 0);
            }
        } else {
            // K-tile never crosses a tap boundary (768 % 64 == 0)
            int tap = kbase / DM;
            int sh = (tap < 7) ? (tap - 3) : 0;
            int ls = clv + sh;
            bool okr = (ls >= 0 && ls < LL);
            const __half* rowp = g_xnh + (size_t)((cb << 9) + ls) * DM;
            #pragma unroll
            for (int c = 0; c < 2; c++) {
                int k0 = kbase + acq * 8 + c * 32;
                int ii = k0 - tap * DM;
                const __half* pa = okr ? rowp + ii : g_xnh;
                cp16(base + OFF_A + sbaseA + c * 64, pa, okr ? 16 : 0);
            }
        }
        // ---- B (4 cp16) ----
        {
            bool okn = (!NGUARD || brn < N);
            const __half* rowb = Bh + (size_t)brn * K;
            #pragma unroll
            for (int c = 0; c < 4; c++) {
                int k0 = kbase + bcq * 32 + c * 8;
                bool ok = okn && (k0 < K);
                const __half* pb = ok ? rowb + k0 : Bh;
                cp16(base + OFF_B + sbaseB + c * 16, pb, ok ? 16 : 0);
            }
        }
    };

    // compute mapping: 8 warps 2(m) x 4(n); warp tile 32x32
    const int wm = (wid >> 2) * 32, wn = (wid & 3) * 32;
    const uint32_t aB = smemU + OFF_A + (uint32_t)(wm + (lane & 15)) * ROWB + ((lane >> 4) * 8) * 2;
    const uint32_t bB = smemU + OFF_B
                      + (uint32_t)(wn + ((lane >> 4) & 1) * 8 + (lane & 7)) * ROWB
                      + (((lane >> 3) & 1) * 8) * 2;

    float acc[2][4][4] = {};

    cpAll(0, 0); CP_COMMIT();
    CP_WAIT0();
    __syncthreads();

    for (int kt = 0; kt < nk; kt++) {
        const int cur = kt & 1, nx = cur ^ 1;
        const bool more = (kt + 1 < nk);
        if (more) { cpAll(kt + 1, nx); CP_COMMIT(); }

        const uint32_t so = cur * SSTR;
        #pragma unroll
        for (int s = 0; s < 4; s++) {
            uint32_t a[2][4], b[4][2];
            #pragma unroll
            for (int i = 0; i < 2; i++)
                ldsm4(a[i][0], a[i][1], a[i][2], a[i][3], aB + so + i * 16 * ROWB + s * 32);
            #pragma unroll
            for (int p = 0; p < 2; p++)
                ldsm4(b[2 * p][0], b[2 * p][1], b[2 * p + 1][0], b[2 * p + 1][1],
                      bB + so + p * 16 * ROWB + s * 32);
            #pragma unroll
            for (int i = 0; i < 2; i++)
                #pragma unroll
                for (int j = 0; j < 4; j++) {
                    float* c = acc[i][j];
                    mma_f16(c[0], c[1], c[2], c[3], a[i], b[j]);
                }
        }
        if (more) {
            CP_WAIT0();
            __syncthreads();
        }
    }

    // ---- epilogue ---------------------------------------------------------
    const int gr = lane >> 2, t4 = lane & 3;
    #pragma unroll
    for (int i = 0; i < 2; i++) {
        #pragma unroll
        for (int j = 0; j < 4; j++) {
            const int col = bn + wn + j * 8 + 2 * t4;
            if (NGUARD && col >= N) continue;
            const int row0 = bm + wm + i * 16 + gr;
            float b0 = 0.f, b1 = 0.f;
            if (BIAS) { b0 = bias[col]; b1 = bias[col + 1]; }
            #pragma unroll
            for (int h = 0; h < 2; h++) {
                const int r = row0 + h * 8;
                float v0 = acc[i][j][2 * h + 0] + b0;
                float v1 = acc[i][j][2 * h + 1] + b1;
                if (ACT == 1) {
                    v0 = (v0 > 20.f) ? v0 : log1pf(__expf(v0));
                    v1 = (v1 > 20.f) ? v1 : log1pf(__expf(v1));
                }
                if (ACT == 2) {
                    const float* arw = Afp + (size_t)r * ldafp;
                    float g0 = 1.f / (1.f + __expf(-v0));
                    float g1 = 1.f / (1.f + __expf(-v1));
                    v0 = g0 * arw[col]     + (1.f - g0) * arw[DM + col];
                    v1 = g1 * arw[col + 1] + (1.f - g1) * arw[DM + col + 1];
                }
                if (WF) {
                    float* cp = Cf + (size_t)r * ldc + col;
                    cp[0] = v0; cp[1] = v1;
                }
                if (WH) {
                    *(__half2*)(Ch + (size_t)r * ldc + col) =
                        __floats2half2_rn(v0, v1);
                }
            }
        }
    }
}

// standalone GEMM kernel
template<int MODEA, bool BIAS, int ACT, bool NGUARD, bool WF, bool WH>
__global__ __launch_bounds__(256) void mgemm_k(
    const __half* __restrict__ Ah, int lda,
    const __half* __restrict__ Bh,
    const float* __restrict__ bias,
    float* __restrict__ Cf, __half* __restrict__ Ch,
    int ldc, int N, int K,
    const float* __restrict__ Afp, int ldafp)
{
    extern __shared__ __align__(16) char smem[];
    mgemm_body<MODEA, BIAS, ACT, NGUARD, WF, WH>(
        Ah, lda, Bh, bias, Cf, Ch, ldc, N, K, Afp, ldafp,
        blockIdx.y * 64, blockIdx.x * 128, smem);
}

// fat kernel: conv+gcn GEMM (x<6) and in_proj GEMM (x>=6), both read g_xnh
__global__ __launch_bounds__(256) void fat_k(
    const __half* __restrict__ xnh,
    const __half* __restrict__ wcv, const float* __restrict__ cbias,
    float* __restrict__ cat, __half* __restrict__ cath,
    const __half* __restrict__ win, float* __restrict__ xz)
{
    extern __shared__ __align__(16) char smem[];
    if (blockIdx.x < 6) {
        mgemm_body<1, true, 0, false, true, true>(
            nullptr, 0, wcv, cbias, cat, cath, 2 * DM, DM, 8 * DM, nullptr, 0,
            blockIdx.y * 64, blockIdx.x * 128, smem);
    } else {
        mgemm_body<0, false, 0, false, true, false>(
            xnh, DM, win, nullptr, xz, nullptr, 2 * DI, 2 * DI, DM, nullptr, 0,
            blockIdx.y * 64, (blockIdx.x - 6) * 128, smem);
    }
}

// ============== weight transpose to fp16 ===================================
__global__ __launch_bounds__(256) void wsplit_k(
    const float* __restrict__ W, __half* __restrict__ oh,
    int K, int N, int ldo, int koff)
{
    __shared__ float t[32][33];
    const int kb = blockIdx.y * 32, nb = blockIdx.x * 32;
    const int tx = threadIdx.x & 31, ty = threadIdx.x >> 5;
    #pragma unroll
    for (int r = 0; r < 4; r++) {
        int k = kb + ty + r * 8, n = nb + tx;
        t[ty + r * 8][tx] = (k < K && n < N) ? W[(size_t)k * N + n] : 0.f;
    }
    __syncthreads();
    #pragma unroll
    for (int r = 0; r < 4; r++) {
        int n = nb + ty + r * 8, k = kb + tx;
        if (n < N && k < K)
            oh[(size_t)n * ldo + koff + k] = __float2half_rn(t[tx][ty + r * 8]);
    }
}

// combined conv+gcn weight: [o][t*DM+i]; t<7 = conv tap, t==7 = gcn
// also folds the two bias sums (idx < DM)
__global__ void cvsplit_k(const float* __restrict__ cw, const float* __restrict__ gw,
                          const float* __restrict__ cb, const float* __restrict__ gb,
                          const float* __restrict__ ggb, const float* __restrict__ gmb)
{
    int idx = blockIdx.x * blockDim.x + threadIdx.x;
    if (idx >= DM * 8 * DM) return;
    if (idx < DM) {
        g_cbias[idx] = cb[idx] + gb[idx];
        g_gateb[idx] = ggb[idx] + gmb[idx];
    }
    int o = idx / (8 * DM);
    int r = idx - o * (8 * DM);
    int t = r / DM;
    int i = r - t * DM;
    float v = (t < 7) ? cw[(size_t)(o * DM + i) * KSP + t] : gw[(size_t)i * DM + o];
    g_wT_cv[idx] = __float2half_rn(v);
}

// ---------------- layernorm: fp32 out and/or fp16 out ---------------------
__global__ __launch_bounds__(256) void ln_k(
    const float* __restrict__ x, const float* __restrict__ res,
    const float* __restrict__ w, const float* __restrict__ b,
    float* __restrict__ outf, __half* __restrict__ outh)
{
    int row = blockIdx.x;
    const float* xr = x + (size_t)row * DM;
    float v[3];
    float s = 0.f, s2 = 0.f;
    #pragma unroll
    for (int i = 0; i < 3; i++) {
        int c = threadIdx.x + i * 256;
        float t = xr[c];
        if (res) t += res[(size_t)row * DM + c];
        v[i] = t; s += t; s2 += t * t;
    }
    int lane = threadIdx.x & 31, wid = threadIdx.x >> 5;
    #pragma unroll
    for (int o = 16; o >= 1; o >>= 1) {
        s  += __shfl_xor_sync(0xffffffffu, s,  o);
        s2 += __shfl_xor_sync(0xffffffffu, s2, o);
    }
    __shared__ float sa[8], sb2[8];
    if (lane == 0) { sa[wid] = s; sb2[wid] = s2; }
    __syncthreads();
    if (wid == 0) {
        s  = (lane < 8) ? sa[lane] : 0.f;
        s2 = (lane < 8) ? sb2[lane] : 0.f;
        #pragma unroll
        for (int o = 4; o >= 1; o >>= 1) {
            s  += __shfl_xor_sync(0xffffffffu, s,  o);
            s2 += __shfl_xor_sync(0xffffffffu, s2, o);
        }
        if (lane == 0) { sa[0] = s; sb2[0] = s2; }
    }
    __syncthreads();
    float mean = sa[0] * (1.f / DM);
    float var  = sb2[0] * (1.f / DM) - mean * mean;
    float rstd = rsqrtf(var + 1e-5f);
    #pragma unroll
    for (int i = 0; i < 3; i++) {
        int c = threadIdx.x + i * 256;
        float o = (v[i] - mean) * rstd * w[c] + b[c];
        size_t idx = (size_t)row * DM + c;
        if (outf) outf[idx] = o;
        if (outh) outh[idx] = __float2half_rn(o);
    }
}

// ---------------- depthwise causal conv + bias + silu ---------------------
__global__ void dwconv_k(const float* __restrict__ w, const float* __restrict__ bias)
{
    int idx = blockIdx.x * blockDim.x + threadIdx.x;
    if (idx >= BL * DI) return;
    int d = idx % DI;
    int row = idx / DI;
    int l = row & 511, bb = row >> 9;
    float s = bias[d];
    #pragma unroll
    for (int j = 0; j < DCV; j++) {
        int ls = l - 3 + j;
        if (ls >= 0)
            s += g_xz[((size_t)(bb * LL + ls)) * 2 * DI + d] * w[d * DCV + j];
    }
    float sg = 1.f / (1.f + __expf(-s));
    float v = s * sg;
    g_xmc[idx] = v;
    g_xmch[idx] = __float2half_rn(v);
}

// ---------------- selective scan ------------------------------------------
__global__ __launch_bounds__(256) void scan_k(
    const float* __restrict__ A_log, const float* __restrict__ Dvec)
{
    int tid = threadIdx.x;
    int n = tid & 15;
    int d = blockIdx.x * 16 + (tid >> 4);
    int b = blockIdx.y;
    float A = -__expf(A_log[d * NS + n]);
    float Dd = Dvec[d];
    float h = 0.f;
    const float* dtp = g_dtb  + (size_t)b * LL * DI + d;
    const float* xp  = g_xmc  + (size_t)b * LL * DI + d;
    const float* zp  = g_xz   + (size_t)b * LL * 2 * DI + DI + d;
    const float* dbl = g_xdbl + (size_t)b * LL * 80;
    size_t ybase = (size_t)b * LL * DI + d;
    for (int l = 0; l < LL; l++) {
        float dtv = dtp[(size_t)l * DI];
        float xv  = xp[(size_t)l * DI];
        float Bn  = dbl[l * 80 + 48 + n];
        float Cn  = dbl[l * 80 + 64 + n];
        h = __expf(dtv * A) * h + dtv * Bn * xv;
        float p = h * Cn;
        #pragma unroll
        for (int o = 8; o >= 1; o >>= 1)
            p += __shfl_xor_sync(0xffffffffu, p, o, 16);
        if (n == 0) {
            float zv = zp[(size_t)l * 2 * DI];
            float sz = zv / (1.f + __expf(-zv));
            g_yh[ybase + (size_t)l * DI] = __float2half_rn((p + Dd * xv) * sz);
        }
    }
}

// ---------------- adjacency ------------------------------------------------
__global__ void adj_k(const float* __restrict__ nv1, const float* __restrict__ nv2,
                      float* __restrict__ out)
{
    int idx = blockIdx.x * blockDim.x + threadIdx.x;
    if (idx >= 64 * 64) return;
    int i = idx >> 6, j = idx & 63;
    float s = 0.f;
    #pragma unroll
    for (int k = 0; k < 16; k++) s += nv1[i * 16 + k] * nv2[k * 64 + j];
    float a = 1.f / (1.f + __expf(-s));
    out[idx] = (i == j) ? 0.f : a;
}

// ---------------- host launch ---------------------------------------------
extern "C" void kernel_launch(void* const* d_in, const int* in_sizes, int n_in,
                              void* d_out, int out_size)
{
    const float* x        = (const float*)d_in[0];
    const float* nv1      = (const float*)d_in[1];
    const float* nv2      = (const float*)d_in[2];
    const float* norm1_w  = (const float*)d_in[3];
    const float* norm1_b  = (const float*)d_in[4];
    const float* norm2_w  = (const float*)d_in[5];
    const float* norm2_b  = (const float*)d_in[6];
    const float* gcn_w    = (const float*)d_in[7];
    const float* gcn_b    = (const float*)d_in[8];
    const float* conv_w   = (const float*)d_in[9];
    const float* conv_b   = (const float*)d_in[10];
    const float* gg_w     = (const float*)d_in[11];
    const float* gg_b     = (const float*)d_in[12];
    const float* gm_w     = (const float*)d_in[13];
    const float* gm_b     = (const float*)d_in[14];
    const float* out_w    = (const float*)d_in[15];
    const float* out_b    = (const float*)d_in[16];
    const float* m_in_w   = (const float*)d_in[17];
    const float* m_conv_w = (const float*)d_in[18];
    const float* m_conv_b = (const float*)d_in[19];
    const float* m_xproj_w= (const float*)d_in[20];
    const float* m_dt_w   = (const float*)d_in[21];
    const float* m_dt_b   = (const float*)d_in[22];
    const float* m_A_log  = (const float*)d_in[23];
    const float* m_D      = (const float*)d_in[24];
    const float* m_out_w  = (const float*)d_in[25];
    float* out = (float*)d_out;

    float *xz, *xmc, *xdbl, *dtb, *cat, *tmp, *cbias, *gateb;
    cudaGetSymbolAddress((void**)&xz,    g_xz);
    cudaGetSymbolAddress((void**)&xmc,   g_xmc);
    cudaGetSymbolAddress((void**)&xdbl,  g_xdbl);
    cudaGetSymbolAddress((void**)&dtb,   g_dtb);
    cudaGetSymbolAddress((void**)&cat,   g_cat);
    cudaGetSymbolAddress((void**)&tmp,   g_tmp);
    cudaGetSymbolAddress((void**)&cbias, g_cbias);
    cudaGetSymbolAddress((void**)&gateb, g_gateb);

    __half *xnh, *xmch, *xdblh, *yh, *cath, *fusedh;
    cudaGetSymbolAddress((void**)&xnh,   g_xnh);
    cudaGetSymbolAddress((void**)&xmch,  g_xmch);
    cudaGetSymbolAddress((void**)&xdblh, g_xdblh);
    cudaGetSymbolAddress((void**)&yh,    g_yh);
    cudaGetSymbolAddress((void**)&cath,  g_cath);
    cudaGetSymbolAddress((void**)&fusedh,g_fusedh);

    __half *win, *wdt, *wout, *wggm, *wo, *wxp, *wcv;
    cudaGetSymbolAddress((void**)&win,  g_wT_in);
    cudaGetSymbolAddress((void**)&wdt,  g_wT_dt);
    cudaGetSymbolAddress((void**)&wout, g_wT_out);
    cudaGetSymbolAddress((void**)&wggm, g_wT_ggm);
    cudaGetSymbolAddress((void**)&wo,   g_wT_o);
    cudaGetSymbolAddress((void**)&wxp,  g_wT_xp);
    cudaGetSymbolAddress((void**)&wcv,  g_wT_cv);

    cudaFuncSetAttribute(fat_k, cudaFuncAttributeMaxDynamicSharedMemorySize, MG_SMEM);
    cudaFuncSetAttribute(mgemm_k<0, false, 0, true,  true,  true >, cudaFuncAttributeMaxDynamicSharedMemorySize, MG_SMEM);
    cudaFuncSetAttribute(mgemm_k<0, true,  1, false, true,  false>, cudaFuncAttributeMaxDynamicSharedMemorySize, MG_SMEM);
    cudaFuncSetAttribute(mgemm_k<0, false, 0, false, true,  true >, cudaFuncAttributeMaxDynamicSharedMemorySize, MG_SMEM);
    cudaFuncSetAttribute(mgemm_k<0, true,  2, false, false, true >, cudaFuncAttributeMaxDynamicSharedMemorySize, MG_SMEM);
    cudaFuncSetAttribute(mgemm_k<0, true,  0, false, true,  false>, cudaFuncAttributeMaxDynamicSharedMemorySize, MG_SMEM);

    // ---- order: my 4th launch = FAT GEMM (ncu captures overall #6) --------
    cvsplit_k<<<(DM * 8 * DM + 255) / 256, 256>>>(conv_w, gcn_w,
                                                  conv_b, gcn_b, gg_b, gm_b);  // 1
    ln_k<<<BL, 256>>>(x, nullptr, norm1_w, norm1_b, nullptr, xnh);             // 2
    wsplit_k<<<dim3(2 * DI / 32, DM / 32), 256>>>(m_in_w, win, DM, 2 * DI, DM, 0); // 3
    // 4: FAT kernel — conv+gcn GEMM (K=6144) and in_proj GEMM (N=3072)
    fat_k<<<dim3(30, BL / 64), 256, MG_SMEM>>>(xnh, wcv, cbias, cat, cath, win, xz);

    adj_k<<<16, 256>>>(nv1, nv2, out + (size_t)BL * DM);

    // remaining weight transposes
    wsplit_k<<<dim3((80 + 31) / 32, DI / 32), 256>>>(m_xproj_w, wxp, DI, 80, DI, 0);
    wsplit_k<<<dim3(DI / 32, (DTR + 31) / 32), 256>>>(m_dt_w, wdt, DTR, DI, DTR, 0);
    wsplit_k<<<dim3(DM / 32, DI / 32), 256>>>(m_out_w, wout, DI, DM, DI, 0);
    wsplit_k<<<dim3(DM / 32, DM / 32), 256>>>(gg_w, wggm, DM, DM, 2 * DM, 0);
    wsplit_k<<<dim3(DM / 32, DM / 32), 256>>>(gm_w, wggm, DM, DM, 2 * DM, DM);
    wsplit_k<<<dim3(DM / 32, DM / 32), 256>>>(out_w, wo, DM, DM, DM, 0);

    // depthwise causal conv + bias + silu
    dwconv_k<<<(BL * DI + 255) / 256, 256>>>(m_conv_w, m_conv_b);

    // x_dbl = xmc @ m_xproj_w  (N = 80)
    mgemm_k<0, false, 0, true, true, true><<<dim3(1, BL / 64), 256, MG_SMEM>>>(
        xmch, DI, wxp, nullptr, xdbl, xdblh, 80, 80, DI, nullptr, 0);

    // dt = softplus(x_dbl[:, :48] @ m_dt_w + m_dt_b)
    mgemm_k<0, true, 1, false, true, false><<<dim3(DI / 128, BL / 64), 256, MG_SMEM>>>(
        xdblh, 80, wdt, m_dt_b, dtb, nullptr, DI, DI, DTR, nullptr, 0);

    // selective scan -> y fp16
    scan_k<<<dim3(DI / 16, BB), 256>>>(m_A_log, m_D);

    // x_mamba = y @ m_out_w -> cat[:, 768:]
    mgemm_k<0, false, 0, false, true, true><<<dim3(DM / 128, BL / 64), 256, MG_SMEM>>>(
        yh, DI, wout, nullptr, cat + DM, cath + DM, 2 * DM, DM, DI, nullptr, 0);

    // gate GEMM (K=1536) with fused sigmoid-mix -> fused fp16
    mgemm_k<0, true, 2, false, false, true><<<dim3(DM / 128, BL / 64), 256, MG_SMEM>>>(
        cath, 2 * DM, wggm, gateb, nullptr, fusedh, DM, DM, 2 * DM, cat, 2 * DM);

    // out = fused @ out_w + out_b -> tmp
    mgemm_k<0, true, 0, false, true, false><<<dim3(DM / 128, BL / 64), 256, MG_SMEM>>>(
        fusedh, DM, wo, out_b, tmp, nullptr, DM, DM, DM, nullptr, 0);

    // LN2(tmp + x) -> out
    ln_k<<<BL, 256>>>(tmp, x, norm2_w, norm2_b, out, nullptr);
}

// round 17
// speedup vs baseline: 1.1183x; 1.1183x over previous
#include <cuda_runtime.h>
#include <cuda_fp16.h>
#include <math.h>
#include <stdint.h>

#define BB   8
#define LL   512
#define BL   4096      // B*L
#define DM   768
#define DI   1536
#define NS   16
#define DTR  48
#define KSP  7
#define DCV  4

// ---------------- scratch (device globals; no allocation allowed) ----------
__device__ float g_xmc[BL * DI];
__device__ float g_xdbl[BL * 80];
__device__ float g_dtb[BL * DI];
__device__ float g_cat[BL * 2 * DM];   // [xgcn | xmamba]
__device__ float g_tmp[BL * DM];
__device__ float g_cbias[DM];          // conv_b + gcn_b
__device__ float g_gateb[DM];          // gg_b + gm_b

// fp16 activation buffers
__device__ __half g_xnh[BL * DM];
__device__ __half g_xzh[BL * 2 * DI];  // in_proj output [x | z] fp16
__device__ __half g_xmch[BL * DI];
__device__ __half g_xdblh[BL * 80];
__device__ __half g_yh[BL * DI];
__device__ __half g_cath[BL * 2 * DM];
__device__ __half g_fusedh[BL * DM];

// pre-transposed weights: [N][K] fp16
__device__ __half g_wT_in[2 * DI * DM];
__device__ __half g_wT_dt[DI * DTR];
__device__ __half g_wT_out[DM * DI];
__device__ __half g_wT_ggm[DM * 2 * DM];
__device__ __half g_wT_o[DM * DM];
__device__ __half g_wT_xp[80 * DI];
__device__ __half g_wT_cv[DM * 8 * DM];   // 7 conv taps + gcn

// ===================== helpers =============================================
__device__ __forceinline__ uint32_t s2u(const void* p) {
    uint32_t a;
    asm("{ .reg .u64 t; cvta.to.shared.u64 t, %1; cvt.u32.u64 %0, t; }" : "=r"(a) : "l"(p));
    return a;
}
__device__ __forceinline__ void ldsm4(uint32_t& r0, uint32_t& r1, uint32_t& r2, uint32_t& r3,
                                      uint32_t addr) {
    asm volatile("ldmatrix.sync.aligned.m8n8.x4.shared.b16 {%0,%1,%2,%3}, [%4];"
        : "=r"(r0), "=r"(r1), "=r"(r2), "=r"(r3) : "r"(addr));
}
__device__ __forceinline__ void mma_f16(float& c0, float& c1, float& c2, float& c3,
                                        const uint32_t* a, const uint32_t* b) {
    asm volatile("mma.sync.aligned.m16n8k16.row.col.f32.f16.f16.f32 "
        "{%0,%1,%2,%3}, {%4,%5,%6,%7}, {%8,%9}, {%0,%1,%2,%3};"
        : "+f"(c0), "+f"(c1), "+f"(c2), "+f"(c3)
        : "r"(a[0]), "r"(a[1]), "r"(a[2]), "r"(a[3]), "r"(b[0]), "r"(b[1]));
}
__device__ __forceinline__ void cp16(uint32_t dst, const void* src, int sz) {
    asm volatile("cp.async.cg.shared.global [%0], [%1], 16, %2;"
        :: "r"(dst), "l"(src), "r"(sz));
}
#define CP_COMMIT() asm volatile("cp.async.commit_group;" ::: "memory")
#define CP_WAIT0()  asm volatile("cp.async.wait_group 0;" ::: "memory")

// smem tiles: A 64 rows x 64 f16, B 128 rows x 64 f16, row stride 144B
constexpr int ROWB = 144;
constexpr int ATILE = 64 * ROWB;                   // 9216
constexpr int BTILE = 128 * ROWB;                  // 18432
constexpr int OFF_A = 0, OFF_B = ATILE;
constexpr int SSTR = ATILE + BTILE;                // 27648
constexpr int MG_SMEM = 2 * SSTR;                  // 55296 -> 4 CTAs/SM

// ===================== tensor-core GEMM (mma.sync fp16) ====================
// C[M,N] = A[M,K] @ BT[N,K]^T ; A fp16, BT fp16, fp32 accumulate.
// Block tile 64(M) x 128(N), K-tile 64, double-buffered cp.async.
// MODEA: 0 = A from Ah; 1 = conv-shifted gather of g_xnh (K=8*DM).
// ACT: 0=none, 1=softplus, 2=gated fusion. WF/WH: fp32 / fp16 C writes.
template<int MODEA, bool BIAS, int ACT, bool NGUARD, bool WF, bool WH>
__global__ __launch_bounds__(256) void mgemm_k(
    const __half* __restrict__ Ah, int lda,
    const __half* __restrict__ Bh,
    const float* __restrict__ bias,
    float* __restrict__ Cf, __half* __restrict__ Ch,
    int ldc, int N, int K,
    const float* __restrict__ Afp, int ldafp)
{
    extern __shared__ __align__(16) char smem[];
    const uint32_t smemU = s2u(smem);
    const int tid = threadIdx.x, wid = tid >> 5, lane = tid & 31;
    const int bm = blockIdx.y * 64, bn = blockIdx.x * 128;

    // A loader: thread t -> row t>>2, chunks (t&3) and (t&3)+4 (16B each)
    const int arow = tid >> 2;
    const int acq  = (tid & 3);
    const int ar = bm + arow;
    const int cb = ar >> 9, clv = ar & 511;   // conv coords
    const uint32_t sbaseA = arow * ROWB + acq * 16;
    // B loader: thread t -> row t>>1, 64B half (t&1) = 4 chunks
    const int brow = tid >> 1;
    const int bcq  = (tid & 1);
    const int brn = bn + brow;
    const uint32_t sbaseB = brow * ROWB + bcq * 64;

    const int nk = (K + 63) >> 6;

    auto cpAll = [&](int kt, int stg) {
        const uint32_t base = smemU + stg * SSTR;
        const int kbase = kt * 64;
        // ---- A (2 cp16) ----
        if (MODEA == 0) {
            #pragma unroll
            for (int c = 0; c < 2; c++) {
                int k0 = kbase + acq * 8 + c * 32;
                bool ok = (k0 < K);
                const __half* pa = ok ? Ah + (size_t)ar * lda + k0 : g_xnh;
                cp16(base + OFF_A + sbaseA + c * 64, pa, ok ? 16 : 0);
            }
        } else {
            // K-tile never crosses a tap boundary (768 % 64 == 0)
            int tap = kbase / DM;
            int sh = (tap < 7) ? (tap - 3) : 0;
            int ls = clv + sh;
            bool okr = (ls >= 0 && ls < LL);
            const __half* rowp = g_xnh + (size_t)((cb << 9) + ls) * DM;
            #pragma unroll
            for (int c = 0; c < 2; c++) {
                int k0 = kbase + acq * 8 + c * 32;
                int ii = k0 - tap * DM;
                const __half* pa = okr ? rowp + ii : g_xnh;
                cp16(base + OFF_A + sbaseA + c * 64, pa, okr ? 16 : 0);
            }
        }
        // ---- B (4 cp16) ----
        {
            bool okn = (!NGUARD || brn < N);
            const __half* rowb = Bh + (size_t)brn * K;
            #pragma unroll
            for (int c = 0; c < 4; c++) {
                int k0 = kbase + bcq * 32 + c * 8;
                bool ok = okn && (k0 < K);
                const __half* pb = ok ? rowb + k0 : Bh;
                cp16(base + OFF_B + sbaseB + c * 16, pb, ok ? 16 : 0);
            }
        }
    };

    // compute mapping: 8 warps 2(m) x 4(n); warp tile 32x32
    const int wm = (wid >> 2) * 32, wn = (wid & 3) * 32;
    const uint32_t aB = smemU + OFF_A + (uint32_t)(wm + (lane & 15)) * ROWB + ((lane >> 4) * 8) * 2;
    const uint32_t bB = smemU + OFF_B
                      + (uint32_t)(wn + ((lane >> 4) & 1) * 8 + (lane & 7)) * ROWB
                      + (((lane >> 3) & 1) * 8) * 2;

    float acc[2][4][4] = {};

    cpAll(0, 0); CP_COMMIT();
    CP_WAIT0();
    __syncthreads();

    for (int kt = 0; kt < nk; kt++) {
        const int cur = kt & 1, nx = cur ^ 1;
        const bool more = (kt + 1 < nk);
        if (more) { cpAll(kt + 1, nx); CP_COMMIT(); }

        const uint32_t so = cur * SSTR;
        #pragma unroll
        for (int s = 0; s < 4; s++) {
            uint32_t a[2][4], b[4][2];
            #pragma unroll
            for (int i = 0; i < 2; i++)
                ldsm4(a[i][0], a[i][1], a[i][2], a[i][3], aB + so + i * 16 * ROWB + s * 32);
            #pragma unroll
            for (int p = 0; p < 2; p++)
                ldsm4(b[2 * p][0], b[2 * p][1], b[2 * p + 1][0], b[2 * p + 1][1],
                      bB + so + p * 16 * ROWB + s * 32);
            #pragma unroll
            for (int i = 0; i < 2; i++)
                #pragma unroll
                for (int j = 0; j < 4; j++) {
                    float* c = acc[i][j];
                    mma_f16(c[0], c[1], c[2], c[3], a[i], b[j]);
                }
        }
        if (more) {
            CP_WAIT0();
            __syncthreads();
        }
    }

    // ---- epilogue ---------------------------------------------------------
    const int gr = lane >> 2, t4 = lane & 3;
    #pragma unroll
    for (int i = 0; i < 2; i++) {
        #pragma unroll
        for (int j = 0; j < 4; j++) {
            const int col = bn + wn + j * 8 + 2 * t4;
            if (NGUARD && col >= N) continue;
            const int row0 = bm + wm + i * 16 + gr;
            float b0 = 0.f, b1 = 0.f;
            if (BIAS) { b0 = bias[col]; b1 = bias[col + 1]; }
            #pragma unroll
            for (int h = 0; h < 2; h++) {
                const int r = row0 + h * 8;
                float v0 = acc[i][j][2 * h + 0] + b0;
                float v1 = acc[i][j][2 * h + 1] + b1;
                if (ACT == 1) {
                    v0 = (v0 > 20.f) ? v0 : log1pf(__expf(v0));
                    v1 = (v1 > 20.f) ? v1 : log1pf(__expf(v1));
                }
                if (ACT == 2) {
                    const float* arw = Afp + (size_t)r * ldafp;
                    float g0 = 1.f / (1.f + __expf(-v0));
                    float g1 = 1.f / (1.f + __expf(-v1));
                    v0 = g0 * arw[col]     + (1.f - g0) * arw[DM + col];
                    v1 = g1 * arw[col + 1] + (1.f - g1) * arw[DM + col + 1];
                }
                if (WF) {
                    float* cp = Cf + (size_t)r * ldc + col;
                    cp[0] = v0; cp[1] = v1;
                }
                if (WH) {
                    *(__half2*)(Ch + (size_t)r * ldc + col) =
                        __floats2half2_rn(v0, v1);
                }
            }
        }
    }
}

// ============== weight transpose to fp16 ===================================
__global__ __launch_bounds__(256) void wsplit_k(
    const float* __restrict__ W, __half* __restrict__ oh,
    int K, int N, int ldo, int koff)
{
    __shared__ float t[32][33];
    const int kb = blockIdx.y * 32, nb = blockIdx.x * 32;
    const int tx = threadIdx.x & 31, ty = threadIdx.x >> 5;
    #pragma unroll
    for (int r = 0; r < 4; r++) {
        int k = kb + ty + r * 8, n = nb + tx;
        t[ty + r * 8][tx] = (k < K && n < N) ? W[(size_t)k * N + n] : 0.f;
    }
    __syncthreads();
    #pragma unroll
    for (int r = 0; r < 4; r++) {
        int n = nb + ty + r * 8, k = kb + tx;
        if (n < N && k < K)
            oh[(size_t)n * ldo + koff + k] = __float2half_rn(t[tx][ty + r * 8]);
    }
}

// combined conv+gcn weight: [o][t*DM+i]; t<7 = conv tap, t==7 = gcn
// also folds the two bias sums (idx < DM)
__global__ void cvsplit_k(const float* __restrict__ cw, const float* __restrict__ gw,
                          const float* __restrict__ cb, const float* __restrict__ gb,
                          const float* __restrict__ ggb, const float* __restrict__ gmb)
{
    int idx = blockIdx.x * blockDim.x + threadIdx.x;
    if (idx >= DM * 8 * DM) return;
    if (idx < DM) {
        g_cbias[idx] = cb[idx] + gb[idx];
        g_gateb[idx] = ggb[idx] + gmb[idx];
    }
    int o = idx / (8 * DM);
    int r = idx - o * (8 * DM);
    int t = r / DM;
    int i = r - t * DM;
    float v = (t < 7) ? cw[(size_t)(o * DM + i) * KSP + t] : gw[(size_t)i * DM + o];
    g_wT_cv[idx] = __float2half_rn(v);
}

// ---------------- layernorm: fp32 out and/or fp16 out ---------------------
__global__ __launch_bounds__(256) void ln_k(
    const float* __restrict__ x, const float* __restrict__ res,
    const float* __restrict__ w, const float* __restrict__ b,
    float* __restrict__ outf, __half* __restrict__ outh)
{
    int row = blockIdx.x;
    const float* xr = x + (size_t)row * DM;
    float v[3];
    float s = 0.f, s2 = 0.f;
    #pragma unroll
    for (int i = 0; i < 3; i++) {
        int c = threadIdx.x + i * 256;
        float t = xr[c];
        if (res) t += res[(size_t)row * DM + c];
        v[i] = t; s += t; s2 += t * t;
    }
    int lane = threadIdx.x & 31, wid = threadIdx.x >> 5;
    #pragma unroll
    for (int o = 16; o >= 1; o >>= 1) {
        s  += __shfl_xor_sync(0xffffffffu, s,  o);
        s2 += __shfl_xor_sync(0xffffffffu, s2, o);
    }
    __shared__ float sa[8], sb2[8];
    if (lane == 0) { sa[wid] = s; sb2[wid] = s2; }
    __syncthreads();
    if (wid == 0) {
        s  = (lane < 8) ? sa[lane] : 0.f;
        s2 = (lane < 8) ? sb2[lane] : 0.f;
        #pragma unroll
        for (int o = 4; o >= 1; o >>= 1) {
            s  += __shfl_xor_sync(0xffffffffu, s,  o);
            s2 += __shfl_xor_sync(0xffffffffu, s2, o);
        }
        if (lane == 0) { sa[0] = s; sb2[0] = s2; }
    }
    __syncthreads();
    float mean = sa[0] * (1.f / DM);
    float var  = sb2[0] * (1.f / DM) - mean * mean;
    float rstd = rsqrtf(var + 1e-5f);
    #pragma unroll
    for (int i = 0; i < 3; i++) {
        int c = threadIdx.x + i * 256;
        float o = (v[i] - mean) * rstd * w[c] + b[c];
        size_t idx = (size_t)row * DM + c;
        if (outf) outf[idx] = o;
        if (outh) outh[idx] = __float2half_rn(o);
    }
}

// ---------------- depthwise causal conv + bias + silu (fp16 in) -----------
__global__ void dwconv_k(const float* __restrict__ w, const float* __restrict__ bias)
{
    int idx = blockIdx.x * blockDim.x + threadIdx.x;
    if (idx >= BL * DI) return;
    int d = idx % DI;
    int row = idx / DI;
    int l = row & 511, bb = row >> 9;
    float s = bias[d];
    #pragma unroll
    for (int j = 0; j < DCV; j++) {
        int ls = l - 3 + j;
        if (ls >= 0)
            s += __half2float(g_xzh[((size_t)(bb * LL + ls)) * 2 * DI + d]) * w[d * DCV + j];
    }
    float sg = 1.f / (1.f + __expf(-s));
    float v = s * sg;
    g_xmc[idx] = v;
    g_xmch[idx] = __float2half_rn(v);
}

// ---------------- selective scan v2: 8 lanes/chain, 2 states/lane ----------
// grid (DI/32, BB), 256 threads; chain = (b, d), lane ln = tid&7, n = 2*ln, 2*ln+1
__global__ __launch_bounds__(256) void scan_k(
    const float* __restrict__ A_log, const float* __restrict__ Dvec)
{
    const int tid = threadIdx.x;
    const int ln = tid & 7;             // lane within chain
    const int d  = blockIdx.x * 32 + (tid >> 3);
    const int b  = blockIdx.y;
    const int n0 = ln * 2;

    const float A0 = -__expf(A_log[d * NS + n0]);
    const float A1 = -__expf(A_log[d * NS + n0 + 1]);
    const float Dd = Dvec[d];

    float h0 = 0.f, h1 = 0.f;
    const float* dtp  = g_dtb  + (size_t)b * LL * DI + d;
    const float* xp   = g_xmc  + (size_t)b * LL * DI + d;
    const __half* zp  = g_xzh  + (size_t)b * LL * 2 * DI + DI + d;
    const float* dbl  = g_xdbl + (size_t)b * LL * 80;
    __half* yp        = g_yh   + (size_t)b * LL * DI + d;

    for (int l = 0; l < LL; l++) {
        float dtv = dtp[(size_t)l * DI];
        float xv  = xp[(size_t)l * DI];
        float2 Bn = *(const float2*)(dbl + l * 80 + 48 + n0);
        float2 Cn = *(const float2*)(dbl + l * 80 + 64 + n0);
        float dx = dtv * xv;
        h0 = __expf(dtv * A0) * h0 + dx * Bn.x;
        h1 = __expf(dtv * A1) * h1 + dx * Bn.y;
        float p = h0 * Cn.x + h1 * Cn.y;
        #pragma unroll
        for (int o = 4; o >= 1; o >>= 1)
            p += __shfl_xor_sync(0xffffffffu, p, o, 8);
        if (ln == 0) {
            float zv = __half2float(zp[(size_t)l * 2 * DI]);
            float sz = zv / (1.f + __expf(-zv));
            yp[(size_t)l * DI] = __float2half_rn((p + Dd * xv) * sz);
        }
    }
}

// ---------------- adjacency ------------------------------------------------
__global__ void adj_k(const float* __restrict__ nv1, const float* __restrict__ nv2,
                      float* __restrict__ out)
{
    int idx = blockIdx.x * blockDim.x + threadIdx.x;
    if (idx >= 64 * 64) return;
    int i = idx >> 6, j = idx & 63;
    float s = 0.f;
    #pragma unroll
    for (int k = 0; k < 16; k++) s += nv1[i * 16 + k] * nv2[k * 64 + j];
    float a = 1.f / (1.f + __expf(-s));
    out[idx] = (i == j) ? 0.f : a;
}

// ---------------- host launch ---------------------------------------------
extern "C" void kernel_launch(void* const* d_in, const int* in_sizes, int n_in,
                              void* d_out, int out_size)
{
    const float* x        = (const float*)d_in[0];
    const float* nv1      = (const float*)d_in[1];
    const float* nv2      = (const float*)d_in[2];
    const float* norm1_w  = (const float*)d_in[3];
    const float* norm1_b  = (const float*)d_in[4];
    const float* norm2_w  = (const float*)d_in[5];
    const float* norm2_b  = (const float*)d_in[6];
    const float* gcn_w    = (const float*)d_in[7];
    const float* gcn_b    = (const float*)d_in[8];
    const float* conv_w   = (const float*)d_in[9];
    const float* conv_b   = (const float*)d_in[10];
    const float* gg_w     = (const float*)d_in[11];
    const float* gg_b     = (const float*)d_in[12];
    const float* gm_w     = (const float*)d_in[13];
    const float* gm_b     = (const float*)d_in[14];
    const float* out_w    = (const float*)d_in[15];
    const float* out_b    = (const float*)d_in[16];
    const float* m_in_w   = (const float*)d_in[17];
    const float* m_conv_w = (const float*)d_in[18];
    const float* m_conv_b = (const float*)d_in[19];
    const float* m_xproj_w= (const float*)d_in[20];
    const float* m_dt_w   = (const float*)d_in[21];
    const float* m_dt_b   = (const float*)d_in[22];
    const float* m_A_log  = (const float*)d_in[23];
    const float* m_D      = (const float*)d_in[24];
    const float* m_out_w  = (const float*)d_in[25];
    float* out = (float*)d_out;

    float *xmc, *xdbl, *dtb, *cat, *tmp, *cbias, *gateb;
    cudaGetSymbolAddress((void**)&xmc,   g_xmc);
    cudaGetSymbolAddress((void**)&xdbl,  g_xdbl);
    cudaGetSymbolAddress((void**)&dtb,   g_dtb);
    cudaGetSymbolAddress((void**)&cat,   g_cat);
    cudaGetSymbolAddress((void**)&tmp,   g_tmp);
    cudaGetSymbolAddress((void**)&cbias, g_cbias);
    cudaGetSymbolAddress((void**)&gateb, g_gateb);

    __half *xnh, *xzh, *xmch, *xdblh, *yh, *cath, *fusedh;
    cudaGetSymbolAddress((void**)&xnh,   g_xnh);
    cudaGetSymbolAddress((void**)&xzh,   g_xzh);
    cudaGetSymbolAddress((void**)&xmch,  g_xmch);
    cudaGetSymbolAddress((void**)&xdblh, g_xdblh);
    cudaGetSymbolAddress((void**)&yh,    g_yh);
    cudaGetSymbolAddress((void**)&cath,  g_cath);
    cudaGetSymbolAddress((void**)&fusedh,g_fusedh);

    __half *win, *wdt, *wout, *wggm, *wo, *wxp, *wcv;
    cudaGetSymbolAddress((void**)&win,  g_wT_in);
    cudaGetSymbolAddress((void**)&wdt,  g_wT_dt);
    cudaGetSymbolAddress((void**)&wout, g_wT_out);
    cudaGetSymbolAddress((void**)&wggm, g_wT_ggm);
    cudaGetSymbolAddress((void**)&wo,   g_wT_o);
    cudaGetSymbolAddress((void**)&wxp,  g_wT_xp);
    cudaGetSymbolAddress((void**)&wcv,  g_wT_cv);

    cudaFuncSetAttribute(mgemm_k<1, true,  0, false, true,  true >, cudaFuncAttributeMaxDynamicSharedMemorySize, MG_SMEM);
    cudaFuncSetAttribute(mgemm_k<0, false, 0, false, false, true >, cudaFuncAttributeMaxDynamicSharedMemorySize, MG_SMEM);
    cudaFuncSetAttribute(mgemm_k<0, false, 0, true,  true,  true >, cudaFuncAttributeMaxDynamicSharedMemorySize, MG_SMEM);
    cudaFuncSetAttribute(mgemm_k<0, true,  1, false, true,  false>, cudaFuncAttributeMaxDynamicSharedMemorySize, MG_SMEM);
    cudaFuncSetAttribute(mgemm_k<0, false, 0, false, true,  true >, cudaFuncAttributeMaxDynamicSharedMemorySize, MG_SMEM);
    cudaFuncSetAttribute(mgemm_k<0, true,  2, false, false, true >, cudaFuncAttributeMaxDynamicSharedMemorySize, MG_SMEM);
    cudaFuncSetAttribute(mgemm_k<0, true,  0, false, true,  false>, cudaFuncAttributeMaxDynamicSharedMemorySize, MG_SMEM);

    const dim3 gDM(DM / 128, BL / 64);           // (6, 64) = 384 CTAs

    // ---- order: my 4th launch = conv GEMM (ncu captures overall #6) -------
    cvsplit_k<<<(DM * 8 * DM + 255) / 256, 256>>>(conv_w, gcn_w,
                                                  conv_b, gcn_b, gg_b, gm_b);  // 1
    ln_k<<<BL, 256>>>(x, nullptr, norm1_w, norm1_b, nullptr, xnh);             // 2
    wsplit_k<<<dim3(2 * DI / 32, DM / 32), 256>>>(m_in_w, win, DM, 2 * DI, DM, 0); // 3
    // 4: combined conv+gcn GEMM [K = 6144] -> cat[:, :768] fp32 + fp16
    mgemm_k<1, true, 0, false, true, true><<<gDM, 256, MG_SMEM>>>(
        nullptr, 0, wcv, cbias, cat, cath, 2 * DM, DM, 8 * DM, nullptr, 0);

    // mamba in_proj: xz = xn @ m_in_w  (N = 3072) -> fp16 only
    mgemm_k<0, false, 0, false, false, true><<<dim3(2 * DI / 128, BL / 64), 256, MG_SMEM>>>(
        xnh, DM, win, nullptr, nullptr, xzh, 2 * DI, 2 * DI, DM, nullptr, 0);

    adj_k<<<16, 256>>>(nv1, nv2, out + (size_t)BL * DM);

    // remaining weight transposes
    wsplit_k<<<dim3((80 + 31) / 32, DI / 32), 256>>>(m_xproj_w, wxp, DI, 80, DI, 0);
    wsplit_k<<<dim3(DI / 32, (DTR + 31) / 32), 256>>>(m_dt_w, wdt, DTR, DI, DTR, 0);
    wsplit_k<<<dim3(DM / 32, DI / 32), 256>>>(m_out_w, wout, DI, DM, DI, 0);
    wsplit_k<<<dim3(DM / 32, DM / 32), 256>>>(gg_w, wggm, DM, DM, 2 * DM, 0);
    wsplit_k<<<dim3(DM / 32, DM / 32), 256>>>(gm_w, wggm, DM, DM, 2 * DM, DM);
    wsplit_k<<<dim3(DM / 32, DM / 32), 256>>>(out_w, wo, DM, DM, DM, 0);

    // depthwise causal conv + bias + silu
    dwconv_k<<<(BL * DI + 255) / 256, 256>>>(m_conv_w, m_conv_b);

    // x_dbl = xmc @ m_xproj_w  (N = 80)
    mgemm_k<0, false, 0, true, true, true><<<dim3(1, BL / 64), 256, MG_SMEM>>>(
        xmch, DI, wxp, nullptr, xdbl, xdblh, 80, 80, DI, nullptr, 0);

    // dt = softplus(x_dbl[:, :48] @ m_dt_w + m_dt_b)
    mgemm_k<0, true, 1, false, true, false><<<dim3(DI / 128, BL / 64), 256, MG_SMEM>>>(
        xdblh, 80, wdt, m_dt_b, dtb, nullptr, DI, DI, DTR, nullptr, 0);

    // selective scan v2 -> y fp16
    scan_k<<<dim3(DI / 32, BB), 256>>>(m_A_log, m_D);

    // x_mamba = y @ m_out_w -> cat[:, 768:]
    mgemm_k<0, false, 0, false, true, true><<<dim3(DM / 128, BL / 64), 256, MG_SMEM>>>(
        yh, DI, wout, nullptr, cat + DM, cath + DM, 2 * DM, DM, DI, nullptr, 0);

    // gate GEMM (K=1536) with fused sigmoid-mix -> fused fp16
    mgemm_k<0, true, 2, false, false, true><<<dim3(DM / 128, BL / 64), 256, MG_SMEM>>>(
        cath, 2 * DM, wggm, gateb, nullptr, fusedh, DM, DM, 2 * DM, cat, 2 * DM);

    // out = fused @ out_w + out_b -> tmp
    mgemm_k<0, true, 0, false, true, false><<<dim3(DM / 128, BL / 64), 256, MG_SMEM>>>(
        fusedh, DM, wo, out_b, tmp, nullptr, DM, DM, DM, nullptr, 0);

    // LN2(tmp + x) -> out
    ln_k<<<BL, 256>>>(tmp, x, norm2_w, norm2_b, out, nullptr);
}